// round 13
// baseline (speedup 1.0000x reference)
#include <cuda_runtime.h>
#include <cuda_fp16.h>
#include <stdint.h>

#define HID  2048
#define B_   4
#define S_   4096
#define P_   256
#define D_   128
#define NT   1024
#define MTOK 16384
#define SCALE 0.08838834764831845f

// ---------------- scratch ----------------------------------------------------
__device__ __half g_xh [(long)MTOK*HID];
__device__ __half g_wh [4][(long)HID*HID];
__device__ __half g_qkv[3][(long)MTOK*HID];
__device__ __half g_ca [(long)MTOK*HID];

__device__ __forceinline__ void cpa16(uint32_t d, const void* g) {
    asm volatile("cp.async.cg.shared.global [%0], [%1], 16;" :: "r"(d), "l"(g));
}
__device__ __forceinline__ uint32_t packh2(float a, float b) {
    __half2 h = __floats2half2_rn(a, b);
    return *(uint32_t*)&h;
}

#define LDSM4(r0,r1,r2,r3, addr) \
    asm volatile("ldmatrix.sync.aligned.m8n8.x4.shared.b16 {%0,%1,%2,%3}, [%4];" \
        : "=r"(r0), "=r"(r1), "=r"(r2), "=r"(r3) : "r"(addr))

#define LDSM4T(r0,r1,r2,r3, addr) \
    asm volatile("ldmatrix.sync.aligned.m8n8.x4.trans.shared.b16 {%0,%1,%2,%3}, [%4];" \
        : "=r"(r0), "=r"(r1), "=r"(r2), "=r"(r3) : "r"(addr))

#define MMA(d, a0,a1,a2,a3, b0,b1) \
    asm volatile("mma.sync.aligned.m16n8k16.row.col.f32.f16.f16.f32 " \
        "{%0,%1,%2,%3}, {%4,%5,%6,%7}, {%8,%9}, {%0,%1,%2,%3};" \
        : "+f"((d)[0]), "+f"((d)[1]), "+f"((d)[2]), "+f"((d)[3]) \
        : "r"(a0), "r"(a1), "r"(a2), "r"(a3), "r"(b0), "r"(b1))

// ---------------- FP16 GEMM: C = A @ W_z^T + bias_z --------------------------
// Block 128x128, 8 warps (2x4) of 64x32 warp tiles, BK=64, 3-stage cp.async,
// 2 CTAs/SM. NEW: explicit 2-deep fragment double-buffer across k16-steps.
#define PADH 72
#define BUFH (128 * PADH)
#define GEMM_SMEM (6 * BUFH * 2)   // 110592 B

template<bool OUT_HALF>
__global__ __launch_bounds__(256, 2)
void gemm_fp16(const __half* __restrict__ A, const __half* __restrict__ Wbase,
               const float* __restrict__ bias0, const float* __restrict__ bias1,
               const float* __restrict__ bias2, void* __restrict__ Cv,
               long sW, long sC)
{
    extern __shared__ __half sgm[];
    __half* As = sgm;              // [3][BUFH]
    __half* Bs = sgm + 3 * BUFH;   // [3][BUFH]

    const int z  = blockIdx.x >> 4;
    const int n0 = (blockIdx.x & 15) * 128;
    const int m0 = blockIdx.y * 128;
    const __half* Bm = Wbase + (long)z * sW;
    const float* bias = (z == 0) ? bias0 : (z == 1) ? bias1 : bias2;

    const int tid  = threadIdx.x;
    const int lane = tid & 31;
    const int wid  = tid >> 5;
    const int wm   = wid >> 2;
    const int wn   = wid & 3;
    const int g    = lane >> 2;
    const int tg   = lane & 3;

    float acc[4][4][4];
#pragma unroll
    for (int i = 0; i < 4; i++)
#pragma unroll
        for (int j = 0; j < 4; j++)
#pragma unroll
            for (int r = 0; r < 4; r++) acc[i][j][r] = 0.f;

    const uint32_t sA0 = (uint32_t)__cvta_generic_to_shared(As);
    const uint32_t sB0 = (uint32_t)__cvta_generic_to_shared(Bs);
    const uint32_t aBase = sA0 + (((wm * 64 + (lane & 15)) * PADH) + (lane >> 4) * 8) * 2;
    const uint32_t bBase = sB0 + (((wn * 32 + (lane & 7) + ((lane >> 4) << 3)) * PADH)
                                  + ((lane >> 3) & 1) * 8) * 2;

    // per-thread global bases for the prefetch (row0 = tid>>3, col8 = (tid&7)*8)
    const __half* Ag = A  + (long)(m0 + (tid >> 3)) * HID + ((tid & 7) << 3);
    const __half* Bg = Bm + (long)(n0 + (tid >> 3)) * HID + ((tid & 7) << 3);
    const uint32_t sAw = (uint32_t)__cvta_generic_to_shared(
                             &As[(tid >> 3) * PADH + ((tid & 7) << 3)]);
    const uint32_t sBw = (uint32_t)__cvta_generic_to_shared(
                             &Bs[(tid >> 3) * PADH + ((tid & 7) << 3)]);

    auto prefetch = [&](int kt, int buf) {
#pragma unroll
        for (int u = 0; u < 4; u++) {
            // row advances by 32 per u: +32*HID in global, +32*PADH in smem
            cpa16(sAw + (uint32_t)(buf * BUFH + u * 32 * PADH) * 2,
                  Ag + (long)u * 32 * HID + kt * 64);
            cpa16(sBw + (uint32_t)(buf * BUFH + u * 32 * PADH) * 2,
                  Bg + (long)u * 32 * HID + kt * 64);
        }
        asm volatile("cp.async.commit_group;");
    };

    prefetch(0, 0);
    prefetch(1, 1);

    const int nK = HID >> 6;   // 32 tiles
    int buf = 0, pbuf = 2;
    for (int t = 0; t < nK; t++) {
        if (t + 1 < nK) asm volatile("cp.async.wait_group 1;");
        else            asm volatile("cp.async.wait_group 0;");
        __syncthreads();

        if (t + 2 < nK) prefetch(t + 2, pbuf);

        const uint32_t ak = aBase + (uint32_t)(buf * BUFH * 2);
        const uint32_t bk = bBase + (uint32_t)(buf * BUFH * 2);

        uint32_t af[2][4][4], bf[2][4][2];

        // load k-step 0 fragments into slot 0
#pragma unroll
        for (int mi = 0; mi < 4; mi++)
            LDSM4(af[0][mi][0], af[0][mi][1], af[0][mi][2], af[0][mi][3],
                  ak + (uint32_t)(mi * 16 * PADH * 2));
#pragma unroll
        for (int p = 0; p < 2; p++)
            LDSM4(bf[0][2*p][0], bf[0][2*p][1], bf[0][2*p+1][0], bf[0][2*p+1][1],
                  bk + (uint32_t)(p * 16 * PADH * 2));

#pragma unroll
        for (int ks = 0; ks < 4; ks++) {
            const int cur = ks & 1, nxt = cur ^ 1;
            if (ks < 3) {
                const uint32_t ka = ak + (uint32_t)((ks + 1) * 16 * 2);
                const uint32_t kb = bk + (uint32_t)((ks + 1) * 16 * 2);
#pragma unroll
                for (int mi = 0; mi < 4; mi++)
                    LDSM4(af[nxt][mi][0], af[nxt][mi][1], af[nxt][mi][2], af[nxt][mi][3],
                          ka + (uint32_t)(mi * 16 * PADH * 2));
#pragma unroll
                for (int p = 0; p < 2; p++)
                    LDSM4(bf[nxt][2*p][0], bf[nxt][2*p][1],
                          bf[nxt][2*p+1][0], bf[nxt][2*p+1][1],
                          kb + (uint32_t)(p * 16 * PADH * 2));
            }
#pragma unroll
            for (int mi = 0; mi < 4; mi++)
#pragma unroll
                for (int ni = 0; ni < 4; ni++)
                    MMA(acc[mi][ni],
                        af[cur][mi][0], af[cur][mi][1], af[cur][mi][2], af[cur][mi][3],
                        bf[cur][ni][0], bf[cur][ni][1]);
        }
        buf  = (buf  == 2) ? 0 : buf  + 1;
        pbuf = (pbuf == 2) ? 0 : pbuf + 1;
    }

    const long cOff = (long)z * sC;
#pragma unroll
    for (int mi = 0; mi < 4; mi++) {
#pragma unroll
        for (int ni = 0; ni < 4; ni++) {
            int row = m0 + wm * 64 + mi * 16 + g;
            int col = n0 + wn * 32 + ni * 8 + 2 * tg;
            float b0 = bias[col], b1 = bias[col + 1];
            float v00 = acc[mi][ni][0] + b0;
            float v01 = acc[mi][ni][1] + b1;
            float v10 = acc[mi][ni][2] + b0;
            float v11 = acc[mi][ni][3] + b1;
            if (OUT_HALF) {
                __half* C = (__half*)Cv + cOff;
                *(__half2*)(C + (long)row * HID + col)       = __floats2half2_rn(v00, v01);
                *(__half2*)(C + (long)(row + 8) * HID + col) = __floats2half2_rn(v10, v11);
            } else {
                float* C = (float*)Cv + cOff;
                *(float2*)(C + (long)row * HID + col)       = make_float2(v00, v01);
                *(float2*)(C + (long)(row + 8) * HID + col) = make_float2(v10, v11);
            }
        }
    }
}

// ---------------- fused attention, direct load from g_qkv --------------------
#define PADQ 72
#define PADK 136
#define PADV 136
#define ATT_SMEM ((256*PADQ + 256*PADK + 256*PADV) * 2)   // 176128

__global__ __launch_bounds__(256, 1)
void attn_fused(const __half* __restrict__ qkv, __half* __restrict__ ca)
{
    extern __shared__ __half smn[];
    const int t = blockIdx.y, mh = blockIdx.x;
    const int b = t >> 8, h = (t >> 4) & 15, n = t & 15;
    const int tid = threadIdx.x, lane = tid & 31, w = tid >> 5;
    const int jq = w >> 2, q = w & 3;

    const long rowbase = (long)(b * S_ + n * 256) * HID;
    const __half* qg = qkv + rowbase + h * 128 + mh * 64;
    const __half* kg = qkv + (long)MTOK * HID + rowbase + h * 128;
    const __half* vg = qkv + 2 * (long)MTOK * HID + rowbase + h * 128;

    const uint32_t qsu = (uint32_t)__cvta_generic_to_shared(smn);
    const uint32_t ksu = qsu + 256 * PADQ * 2;
    const uint32_t vsu = ksu + 256 * PADK * 2;

#pragma unroll
    for (int u = 0; u < 8; u++) {
        int id = tid + u * 256, row = id >> 3, seg = id & 7;
        cpa16(qsu + (row * PADQ + seg * 8) * 2, qg + (long)row * HID + seg * 8);
    }
#pragma unroll
    for (int u = 0; u < 8; u++) {
        int id = tid + u * 256, rr = id >> 4, seg = id & 15;
        int row = (rr & 63) + (rr >> 6) * 128;
        cpa16(ksu + (row * PADK + seg * 8) * 2, kg + (long)row * HID + seg * 8);
    }
    asm volatile("cp.async.commit_group;");
#pragma unroll
    for (int u = 0; u < 8; u++) {
        int id = tid + u * 256, rr = id >> 4, seg = id & 15;
        int row = 64 + (rr & 63) + (rr >> 6) * 128;
        cpa16(ksu + (row * PADK + seg * 8) * 2, kg + (long)row * HID + seg * 8);
    }
    asm volatile("cp.async.commit_group;");
#pragma unroll
    for (int u = 0; u < 16; u++) {
        int id = tid + u * 256, row = id >> 4, seg = id & 15;
        cpa16(vsu + (row * PADV + seg * 8) * 2, vg + (long)row * HID + seg * 8);
    }
    asm volatile("cp.async.commit_group;");

    const uint32_t aB = qsu + (((jq * 128 + (lane & 7) + ((lane >> 4) & 1) * 8) * PADQ)
                               + q * 16 + ((lane >> 3) & 1) * 8) * 2;
    const uint32_t kB = ksu + ((((lane & 7) + ((lane >> 3) & 1) * 8) * PADK)
                               + (lane >> 4) * 8) * 2;
    const uint32_t vB = vsu + ((((lane & 7) + ((lane >> 4) & 1) * 8) * PADV)
                               + ((lane >> 3) & 1) * 8) * 2;

    float acc[32][4];
#pragma unroll
    for (int i = 0; i < 32; i++)
        acc[i][0] = acc[i][1] = acc[i][2] = acc[i][3] = 0.f;

    asm volatile("cp.async.wait_group 2;");
    __syncthreads();

    uint32_t qa[8][4];
#pragma unroll
    for (int kk = 0; kk < 8; kk++)
        LDSM4T(qa[kk][0], qa[kk][1], qa[kk][2], qa[kk][3],
               aB + (uint32_t)(kk * 16 * PADQ * 2));

#pragma unroll
    for (int kk = 0; kk < 8; kk++) {
        if (kk == 4) { asm volatile("cp.async.wait_group 1;"); __syncthreads(); }
#pragma unroll
        for (int jk = 0; jk < 2; jk++) {
#pragma unroll
            for (int p = 0; p < 8; p++) {
                uint32_t b0, b1, b2, b3;
                LDSM4T(b0, b1, b2, b3,
                       kB + (uint32_t)(((jk * 128 + kk * 16) * PADK + p * 16) * 2));
                MMA(acc[jk*16 + 2*p],     qa[kk][0], qa[kk][1], qa[kk][2], qa[kk][3], b0, b1);
                MMA(acc[jk*16 + 2*p + 1], qa[kk][0], qa[kk][1], qa[kk][2], qa[kk][3], b2, b3);
            }
        }
    }

    float mx0 = -1e30f, mx1 = -1e30f;
#pragma unroll
    for (int i = 0; i < 32; i++) {
        mx0 = fmaxf(mx0, fmaxf(acc[i][0], acc[i][1]));
        mx1 = fmaxf(mx1, fmaxf(acc[i][2], acc[i][3]));
    }
    mx0 = fmaxf(mx0, __shfl_xor_sync(~0u, mx0, 1));
    mx0 = fmaxf(mx0, __shfl_xor_sync(~0u, mx0, 2));
    mx1 = fmaxf(mx1, __shfl_xor_sync(~0u, mx1, 1));
    mx1 = fmaxf(mx1, __shfl_xor_sync(~0u, mx1, 2));
    float s0 = 0.f, s1 = 0.f;
#pragma unroll
    for (int i = 0; i < 32; i++) {
        acc[i][0] = __expf((acc[i][0] - mx0) * SCALE);
        acc[i][1] = __expf((acc[i][1] - mx0) * SCALE);
        acc[i][2] = __expf((acc[i][2] - mx1) * SCALE);
        acc[i][3] = __expf((acc[i][3] - mx1) * SCALE);
        s0 += acc[i][0] + acc[i][1];
        s1 += acc[i][2] + acc[i][3];
    }
    s0 += __shfl_xor_sync(~0u, s0, 1); s0 += __shfl_xor_sync(~0u, s0, 2);
    s1 += __shfl_xor_sync(~0u, s1, 1); s1 += __shfl_xor_sync(~0u, s1, 2);
    const float inv0 = 1.f / s0, inv1 = 1.f / s1;

    asm volatile("cp.async.wait_group 0;");
    __syncthreads();

    float o[16][4];
#pragma unroll
    for (int i = 0; i < 16; i++)
        o[i][0] = o[i][1] = o[i][2] = o[i][3] = 0.f;

#pragma unroll
    for (int jk = 0; jk < 2; jk++) {
#pragma unroll
        for (int kk2 = 0; kk2 < 8; kk2++) {
            const int t0 = jk * 16 + 2 * kk2, t1 = t0 + 1;
            uint32_t a0 = packh2(acc[t0][0] * inv0, acc[t0][1] * inv0);
            uint32_t a1 = packh2(acc[t0][2] * inv1, acc[t0][3] * inv1);
            uint32_t a2 = packh2(acc[t1][0] * inv0, acc[t1][1] * inv0);
            uint32_t a3 = packh2(acc[t1][2] * inv1, acc[t1][3] * inv1);
#pragma unroll
            for (int p2 = 0; p2 < 8; p2++) {
                uint32_t b0, b1, b2, b3;
                LDSM4(b0, b1, b2, b3,
                      vB + (uint32_t)((((jk * 128 + p2 * 16) * PADV) + kk2 * 16) * 2));
                MMA(o[2*p2],     a0, a1, a2, a3, b0, b1);
                MMA(o[2*p2 + 1], a0, a1, a2, a3, b2, b3);
            }
        }
    }

    const int g = lane >> 2, tg = lane & 3;
    const int p2row = 2 * (mh * 64 + q * 16 + g) + jq;
    __half* cbase = ca + ((long)(b * 4096 + h * 256)) * HID + n * 128;
#pragma unroll
    for (int ni = 0; ni < 16; ni++) {
        int d2 = ni * 8 + 2 * tg;
        *(__half2*)(cbase + (long)p2row * HID + d2)        = __floats2half2_rn(o[ni][0], o[ni][1]);
        *(__half2*)(cbase + (long)(p2row + 16) * HID + d2) = __floats2half2_rn(o[ni][2], o[ni][3]);
    }
}

// ---------------- fused f32->f16 conversion, 2 float4 per thread -------------
#define XN4 ((long)MTOK * HID / 4)
#define WN4 ((long)HID * HID / 4)
#define TOTPAIRS ((XN4 + 4 * WN4) / 2)
__global__ void conv_all(const float* __restrict__ X,
                         const float* __restrict__ W0, const float* __restrict__ W1,
                         const float* __restrict__ W2, const float* __restrict__ W3,
                         __half* __restrict__ xh, __half* __restrict__ wh)
{
    long p = (long)blockIdx.x * 256 + threadIdx.x;
    if (p >= TOTPAIRS) return;
    long i = p * 2;
    const float* src;
    __half* dst;
    long idx;
    if (i < XN4) {
        src = X; dst = xh; idx = i;
    } else {
        long j = i - XN4;
        int wsel = (int)(j / WN4);
        src = (wsel == 0) ? W0 : (wsel == 1) ? W1 : (wsel == 2) ? W2 : W3;
        dst = wh + (long)wsel * (WN4 * 4);
        idx = j - (long)wsel * WN4;
    }
    float4 v0 = ((const float4*)src)[idx];
    float4 v1 = ((const float4*)src)[idx + 1];
    uint4 o;
    o.x = packh2(v0.x, v0.y);
    o.y = packh2(v0.z, v0.w);
    o.z = packh2(v1.x, v1.y);
    o.w = packh2(v1.z, v1.w);
    *(uint4*)(dst + idx * 4) = o;
}

// ---------------- launch -------------------------------------------------------
extern "C" void kernel_launch(void* const* d_in, const int* in_sizes, int n_in,
                              void* d_out, int out_size)
{
    const float* X  = (const float*)d_in[0];
    const float* Wq = (const float*)d_in[1];
    const float* bq = (const float*)d_in[2];
    const float* Wk = (const float*)d_in[3];
    const float* bk = (const float*)d_in[4];
    const float* Wv = (const float*)d_in[5];
    const float* bv = (const float*)d_in[6];
    const float* Wo = (const float*)d_in[7];
    const float* bo = (const float*)d_in[8];
    float* out = (float*)d_out;

    __half *xh, *wh, *qkv, *ca;
    cudaGetSymbolAddress((void**)&xh,  g_xh);
    cudaGetSymbolAddress((void**)&wh,  g_wh);
    cudaGetSymbolAddress((void**)&qkv, g_qkv);
    cudaGetSymbolAddress((void**)&ca,  g_ca);

    cudaFuncSetAttribute(attn_fused, cudaFuncAttributeMaxDynamicSharedMemorySize, ATT_SMEM);
    cudaFuncSetAttribute(gemm_fp16<true>,  cudaFuncAttributeMaxDynamicSharedMemorySize, GEMM_SMEM);
    cudaFuncSetAttribute(gemm_fp16<false>, cudaFuncAttributeMaxDynamicSharedMemorySize, GEMM_SMEM);

    const long WSZ = (long)HID * HID;

    conv_all<<<(int)((TOTPAIRS + 255) / 256), 256>>>(X, Wq, Wk, Wv, Wo, xh, wh);

    gemm_fp16<true><<<dim3(48, 128), 256, GEMM_SMEM>>>(xh, wh, bq, bk, bv, qkv,
                                                       WSZ, (long)MTOK * HID);

    attn_fused<<<dim3(2, NT), 256, ATT_SMEM>>>(qkv, ca);

    gemm_fp16<false><<<dim3(16, 128), 256, GEMM_SMEM>>>(ca, wh + 3 * WSZ, bo, bo, bo, out,
                                                        0, 0);
}

// round 14
// speedup vs baseline: 1.0184x; 1.0184x over previous
#include <cuda_runtime.h>
#include <cuda_fp16.h>
#include <stdint.h>

#define HID  2048
#define B_   4
#define S_   4096
#define P_   256
#define D_   128
#define NT   1024
#define MTOK 16384
#define SCALE 0.08838834764831845f

// ---------------- scratch ----------------------------------------------------
__device__ __half g_xh [(long)MTOK*HID];
__device__ __half g_wh [4][(long)HID*HID];
__device__ __half g_qkv[3][(long)MTOK*HID];
__device__ __half g_ca [(long)MTOK*HID];

__device__ __forceinline__ void cpa16(uint32_t d, const void* g) {
    asm volatile("cp.async.cg.shared.global [%0], [%1], 16;" :: "r"(d), "l"(g));
}
__device__ __forceinline__ uint32_t packh2(float a, float b) {
    __half2 h = __floats2half2_rn(a, b);
    return *(uint32_t*)&h;
}

#define LDSM4(r0,r1,r2,r3, addr) \
    asm volatile("ldmatrix.sync.aligned.m8n8.x4.shared.b16 {%0,%1,%2,%3}, [%4];" \
        : "=r"(r0), "=r"(r1), "=r"(r2), "=r"(r3) : "r"(addr))

#define LDSM4T(r0,r1,r2,r3, addr) \
    asm volatile("ldmatrix.sync.aligned.m8n8.x4.trans.shared.b16 {%0,%1,%2,%3}, [%4];" \
        : "=r"(r0), "=r"(r1), "=r"(r2), "=r"(r3) : "r"(addr))

#define MMA(d, a0,a1,a2,a3, b0,b1) \
    asm volatile("mma.sync.aligned.m16n8k16.row.col.f32.f16.f16.f32 " \
        "{%0,%1,%2,%3}, {%4,%5,%6,%7}, {%8,%9}, {%0,%1,%2,%3};" \
        : "+f"((d)[0]), "+f"((d)[1]), "+f"((d)[2]), "+f"((d)[3]) \
        : "r"(a0), "r"(a1), "r"(a2), "r"(a3), "r"(b0), "r"(b1))

// ---------------- FP16 GEMM: C = A @ W_z^T + bias_z --------------------------
// Block 96x192, 8 warps (2x4) of 48x48 warp tiles, BK=64, 2-stage cp.async,
// 2 CTAs/SM. LDSM 0.083 B/MAC -> crossbar cap 75% (vs 67% for 64x32 tiles).
// Ragged grid: 171 m-blocks x 11 n-blocks, clamped loads, guarded epilogue.
#define PADH 72
#define ABUF (96  * PADH)           // 6912 halves
#define BBUF (192 * PADH)           // 13824 halves
#define GEMM_SMEM ((2*ABUF + 2*BBUF) * 2)   // 82944 B
#define NBLK 11                     // ceil(2048/192)

template<bool OUT_HALF>
__global__ __launch_bounds__(256, 2)
void gemm_fp16(const __half* __restrict__ A, const __half* __restrict__ Wbase,
               const float* __restrict__ bias0, const float* __restrict__ bias1,
               const float* __restrict__ bias2, void* __restrict__ Cv,
               long sW, long sC)
{
    extern __shared__ __half sgm[];
    __half* As = sgm;              // [2][ABUF]
    __half* Bs = sgm + 2 * ABUF;   // [2][BBUF]

    const int z  = blockIdx.x / NBLK;
    const int n0 = (blockIdx.x % NBLK) * 192;
    const int m0 = blockIdx.y * 96;
    const __half* Bm = Wbase + (long)z * sW;
    const float* bias = (z == 0) ? bias0 : (z == 1) ? bias1 : bias2;

    const int tid  = threadIdx.x;
    const int lane = tid & 31;
    const int wid  = tid >> 5;
    const int wm   = wid >> 2;      // 0..1 -> 48-row slab
    const int wn   = wid & 3;       // 0..3 -> 48-col slab
    const int g    = lane >> 2;
    const int tg   = lane & 3;

    float acc[3][6][4];
#pragma unroll
    for (int i = 0; i < 3; i++)
#pragma unroll
        for (int j = 0; j < 6; j++)
#pragma unroll
            for (int r = 0; r < 4; r++) acc[i][j][r] = 0.f;

    const uint32_t sA0 = (uint32_t)__cvta_generic_to_shared(As);
    const uint32_t sB0 = (uint32_t)__cvta_generic_to_shared(Bs);
    const uint32_t aBase = sA0 + (((wm * 48 + (lane & 15)) * PADH) + (lane >> 4) * 8) * 2;
    const uint32_t bBase = sB0 + (((wn * 48 + (lane & 7) + ((lane >> 4) << 3)) * PADH)
                                  + ((lane >> 3) & 1) * 8) * 2;

    // one BK=64 tile: A 96x64 halves (3 cpa16/thr), B 192x64 halves (6 cpa16/thr)
    auto prefetch = [&](int kt, int buf) {
#pragma unroll
        for (int u = 0; u < 3; u++) {
            int id   = tid + u * 256;        // 0..767
            int row  = id >> 3;              // 0..95
            int col8 = (id & 7) << 3;
            int rA   = m0 + row; if (rA > MTOK - 1) rA = MTOK - 1;   // clamp
            cpa16((uint32_t)__cvta_generic_to_shared(&As[buf * ABUF + row * PADH + col8]),
                  A + (long)rA * HID + kt * 64 + col8);
        }
#pragma unroll
        for (int u = 0; u < 6; u++) {
            int id   = tid + u * 256;        // 0..1535
            int row  = id >> 3;              // 0..191
            int col8 = (id & 7) << 3;
            int rB   = n0 + row; if (rB > HID - 1) rB = HID - 1;     // clamp
            cpa16((uint32_t)__cvta_generic_to_shared(&Bs[buf * BBUF + row * PADH + col8]),
                  Bm + (long)rB * HID + kt * 64 + col8);
        }
        asm volatile("cp.async.commit_group;");
    };

    prefetch(0, 0);

    const int nK = HID >> 6;   // 32 tiles
    for (int t = 0; t < nK; t++) {
        asm volatile("cp.async.wait_group 0;");
        __syncthreads();

        if (t + 1 < nK) prefetch(t + 1, (t + 1) & 1);

        const int buf = t & 1;
        const uint32_t aOff = (uint32_t)(buf * ABUF * 2);
        const uint32_t bOff = (uint32_t)(buf * BBUF * 2);
#pragma unroll
        for (int k0 = 0; k0 < 64; k0 += 16) {
            uint32_t af[3][4], bf[6][2];
            const uint32_t ak = aBase + aOff + k0 * 2;
            const uint32_t bk = bBase + bOff + k0 * 2;
#pragma unroll
            for (int mi = 0; mi < 3; mi++)
                LDSM4(af[mi][0], af[mi][1], af[mi][2], af[mi][3],
                      ak + (uint32_t)(mi * 16 * PADH * 2));
#pragma unroll
            for (int p = 0; p < 3; p++)
                LDSM4(bf[2*p][0], bf[2*p][1], bf[2*p+1][0], bf[2*p+1][1],
                      bk + (uint32_t)(p * 16 * PADH * 2));
#pragma unroll
            for (int mi = 0; mi < 3; mi++)
#pragma unroll
                for (int ni = 0; ni < 6; ni++)
                    MMA(acc[mi][ni], af[mi][0], af[mi][1], af[mi][2], af[mi][3],
                        bf[ni][0], bf[ni][1]);
        }
    }

    const long cOff = (long)z * sC;
#pragma unroll
    for (int mi = 0; mi < 3; mi++) {
#pragma unroll
        for (int ni = 0; ni < 6; ni++) {
            int row = m0 + wm * 48 + mi * 16 + g;
            int col = n0 + wn * 48 + ni * 8 + 2 * tg;
            if (col < HID) {
                float b0 = bias[col], b1 = bias[col + 1];
                float v00 = acc[mi][ni][0] + b0;
                float v01 = acc[mi][ni][1] + b1;
                float v10 = acc[mi][ni][2] + b0;
                float v11 = acc[mi][ni][3] + b1;
                if (OUT_HALF) {
                    __half* C = (__half*)Cv + cOff;
                    if (row < MTOK)
                        *(__half2*)(C + (long)row * HID + col) = __floats2half2_rn(v00, v01);
                    if (row + 8 < MTOK)
                        *(__half2*)(C + (long)(row + 8) * HID + col) = __floats2half2_rn(v10, v11);
                } else {
                    float* C = (float*)Cv + cOff;
                    if (row < MTOK)
                        *(float2*)(C + (long)row * HID + col) = make_float2(v00, v01);
                    if (row + 8 < MTOK)
                        *(float2*)(C + (long)(row + 8) * HID + col) = make_float2(v10, v11);
                }
            }
        }
    }
}

// ---------------- fused attention, direct load from g_qkv --------------------
#define PADQ 72
#define PADK 136
#define PADV 136
#define ATT_SMEM ((256*PADQ + 256*PADK + 256*PADV) * 2)   // 176128

__global__ __launch_bounds__(256, 1)
void attn_fused(const __half* __restrict__ qkv, __half* __restrict__ ca)
{
    extern __shared__ __half smn[];
    const int t = blockIdx.y, mh = blockIdx.x;
    const int b = t >> 8, h = (t >> 4) & 15, n = t & 15;
    const int tid = threadIdx.x, lane = tid & 31, w = tid >> 5;
    const int jq = w >> 2, q = w & 3;

    const long rowbase = (long)(b * S_ + n * 256) * HID;
    const __half* qg = qkv + rowbase + h * 128 + mh * 64;
    const __half* kg = qkv + (long)MTOK * HID + rowbase + h * 128;
    const __half* vg = qkv + 2 * (long)MTOK * HID + rowbase + h * 128;

    const uint32_t qsu = (uint32_t)__cvta_generic_to_shared(smn);
    const uint32_t ksu = qsu + 256 * PADQ * 2;
    const uint32_t vsu = ksu + 256 * PADK * 2;

#pragma unroll
    for (int u = 0; u < 8; u++) {
        int id = tid + u * 256, row = id >> 3, seg = id & 7;
        cpa16(qsu + (row * PADQ + seg * 8) * 2, qg + (long)row * HID + seg * 8);
    }
#pragma unroll
    for (int u = 0; u < 8; u++) {
        int id = tid + u * 256, rr = id >> 4, seg = id & 15;
        int row = (rr & 63) + (rr >> 6) * 128;
        cpa16(ksu + (row * PADK + seg * 8) * 2, kg + (long)row * HID + seg * 8);
    }
    asm volatile("cp.async.commit_group;");
#pragma unroll
    for (int u = 0; u < 8; u++) {
        int id = tid + u * 256, rr = id >> 4, seg = id & 15;
        int row = 64 + (rr & 63) + (rr >> 6) * 128;
        cpa16(ksu + (row * PADK + seg * 8) * 2, kg + (long)row * HID + seg * 8);
    }
    asm volatile("cp.async.commit_group;");
#pragma unroll
    for (int u = 0; u < 16; u++) {
        int id = tid + u * 256, row = id >> 4, seg = id & 15;
        cpa16(vsu + (row * PADV + seg * 8) * 2, vg + (long)row * HID + seg * 8);
    }
    asm volatile("cp.async.commit_group;");

    const uint32_t aB = qsu + (((jq * 128 + (lane & 7) + ((lane >> 4) & 1) * 8) * PADQ)
                               + q * 16 + ((lane >> 3) & 1) * 8) * 2;
    const uint32_t kB = ksu + ((((lane & 7) + ((lane >> 3) & 1) * 8) * PADK)
                               + (lane >> 4) * 8) * 2;
    const uint32_t vB = vsu + ((((lane & 7) + ((lane >> 4) & 1) * 8) * PADV)
                               + ((lane >> 3) & 1) * 8) * 2;

    float acc[32][4];
#pragma unroll
    for (int i = 0; i < 32; i++)
        acc[i][0] = acc[i][1] = acc[i][2] = acc[i][3] = 0.f;

    asm volatile("cp.async.wait_group 2;");
    __syncthreads();

    uint32_t qa[8][4];
#pragma unroll
    for (int kk = 0; kk < 8; kk++)
        LDSM4T(qa[kk][0], qa[kk][1], qa[kk][2], qa[kk][3],
               aB + (uint32_t)(kk * 16 * PADQ * 2));

#pragma unroll
    for (int kk = 0; kk < 8; kk++) {
        if (kk == 4) { asm volatile("cp.async.wait_group 1;"); __syncthreads(); }
#pragma unroll
        for (int jk = 0; jk < 2; jk++) {
#pragma unroll
            for (int p = 0; p < 8; p++) {
                uint32_t b0, b1, b2, b3;
                LDSM4T(b0, b1, b2, b3,
                       kB + (uint32_t)(((jk * 128 + kk * 16) * PADK + p * 16) * 2));
                MMA(acc[jk*16 + 2*p],     qa[kk][0], qa[kk][1], qa[kk][2], qa[kk][3], b0, b1);
                MMA(acc[jk*16 + 2*p + 1], qa[kk][0], qa[kk][1], qa[kk][2], qa[kk][3], b2, b3);
            }
        }
    }

    float mx0 = -1e30f, mx1 = -1e30f;
#pragma unroll
    for (int i = 0; i < 32; i++) {
        mx0 = fmaxf(mx0, fmaxf(acc[i][0], acc[i][1]));
        mx1 = fmaxf(mx1, fmaxf(acc[i][2], acc[i][3]));
    }
    mx0 = fmaxf(mx0, __shfl_xor_sync(~0u, mx0, 1));
    mx0 = fmaxf(mx0, __shfl_xor_sync(~0u, mx0, 2));
    mx1 = fmaxf(mx1, __shfl_xor_sync(~0u, mx1, 1));
    mx1 = fmaxf(mx1, __shfl_xor_sync(~0u, mx1, 2));
    float s0 = 0.f, s1 = 0.f;
#pragma unroll
    for (int i = 0; i < 32; i++) {
        acc[i][0] = __expf((acc[i][0] - mx0) * SCALE);
        acc[i][1] = __expf((acc[i][1] - mx0) * SCALE);
        acc[i][2] = __expf((acc[i][2] - mx1) * SCALE);
        acc[i][3] = __expf((acc[i][3] - mx1) * SCALE);
        s0 += acc[i][0] + acc[i][1];
        s1 += acc[i][2] + acc[i][3];
    }
    s0 += __shfl_xor_sync(~0u, s0, 1); s0 += __shfl_xor_sync(~0u, s0, 2);
    s1 += __shfl_xor_sync(~0u, s1, 1); s1 += __shfl_xor_sync(~0u, s1, 2);
    const float inv0 = 1.f / s0, inv1 = 1.f / s1;

    asm volatile("cp.async.wait_group 0;");
    __syncthreads();

    float o[16][4];
#pragma unroll
    for (int i = 0; i < 16; i++)
        o[i][0] = o[i][1] = o[i][2] = o[i][3] = 0.f;

#pragma unroll
    for (int jk = 0; jk < 2; jk++) {
#pragma unroll
        for (int kk2 = 0; kk2 < 8; kk2++) {
            const int t0 = jk * 16 + 2 * kk2, t1 = t0 + 1;
            uint32_t a0 = packh2(acc[t0][0] * inv0, acc[t0][1] * inv0);
            uint32_t a1 = packh2(acc[t0][2] * inv1, acc[t0][3] * inv1);
            uint32_t a2 = packh2(acc[t1][0] * inv0, acc[t1][1] * inv0);
            uint32_t a3 = packh2(acc[t1][2] * inv1, acc[t1][3] * inv1);
#pragma unroll
            for (int p2 = 0; p2 < 8; p2++) {
                uint32_t b0, b1, b2, b3;
                LDSM4(b0, b1, b2, b3,
                      vB + (uint32_t)((((jk * 128 + p2 * 16) * PADV) + kk2 * 16) * 2));
                MMA(o[2*p2],     a0, a1, a2, a3, b0, b1);
                MMA(o[2*p2 + 1], a0, a1, a2, a3, b2, b3);
            }
        }
    }

    const int g = lane >> 2, tg = lane & 3;
    const int p2row = 2 * (mh * 64 + q * 16 + g) + jq;
    __half* cbase = ca + ((long)(b * 4096 + h * 256)) * HID + n * 128;
#pragma unroll
    for (int ni = 0; ni < 16; ni++) {
        int d2 = ni * 8 + 2 * tg;
        *(__half2*)(cbase + (long)p2row * HID + d2)        = __floats2half2_rn(o[ni][0], o[ni][1]);
        *(__half2*)(cbase + (long)(p2row + 16) * HID + d2) = __floats2half2_rn(o[ni][2], o[ni][3]);
    }
}

// ---------------- fused f32->f16 conversion, 2 float4 per thread -------------
#define XN4 ((long)MTOK * HID / 4)
#define WN4 ((long)HID * HID / 4)
#define TOTPAIRS ((XN4 + 4 * WN4) / 2)
__global__ void conv_all(const float* __restrict__ X,
                         const float* __restrict__ W0, const float* __restrict__ W1,
                         const float* __restrict__ W2, const float* __restrict__ W3,
                         __half* __restrict__ xh, __half* __restrict__ wh)
{
    long p = (long)blockIdx.x * 256 + threadIdx.x;
    if (p >= TOTPAIRS) return;
    long i = p * 2;
    const float* src;
    __half* dst;
    long idx;
    if (i < XN4) {
        src = X; dst = xh; idx = i;
    } else {
        long j = i - XN4;
        int wsel = (int)(j / WN4);
        src = (wsel == 0) ? W0 : (wsel == 1) ? W1 : (wsel == 2) ? W2 : W3;
        dst = wh + (long)wsel * (WN4 * 4);
        idx = j - (long)wsel * WN4;
    }
    float4 v0 = ((const float4*)src)[idx];
    float4 v1 = ((const float4*)src)[idx + 1];
    uint4 o;
    o.x = packh2(v0.x, v0.y);
    o.y = packh2(v0.z, v0.w);
    o.z = packh2(v1.x, v1.y);
    o.w = packh2(v1.z, v1.w);
    *(uint4*)(dst + idx * 4) = o;
}

// ---------------- launch -------------------------------------------------------
extern "C" void kernel_launch(void* const* d_in, const int* in_sizes, int n_in,
                              void* d_out, int out_size)
{
    const float* X  = (const float*)d_in[0];
    const float* Wq = (const float*)d_in[1];
    const float* bq = (const float*)d_in[2];
    const float* Wk = (const float*)d_in[3];
    const float* bk = (const float*)d_in[4];
    const float* Wv = (const float*)d_in[5];
    const float* bv = (const float*)d_in[6];
    const float* Wo = (const float*)d_in[7];
    const float* bo = (const float*)d_in[8];
    float* out = (float*)d_out;

    __half *xh, *wh, *qkv, *ca;
    cudaGetSymbolAddress((void**)&xh,  g_xh);
    cudaGetSymbolAddress((void**)&wh,  g_wh);
    cudaGetSymbolAddress((void**)&qkv, g_qkv);
    cudaGetSymbolAddress((void**)&ca,  g_ca);

    cudaFuncSetAttribute(attn_fused, cudaFuncAttributeMaxDynamicSharedMemorySize, ATT_SMEM);
    cudaFuncSetAttribute(gemm_fp16<true>,  cudaFuncAttributeMaxDynamicSharedMemorySize, GEMM_SMEM);
    cudaFuncSetAttribute(gemm_fp16<false>, cudaFuncAttributeMaxDynamicSharedMemorySize, GEMM_SMEM);

    const long WSZ = (long)HID * HID;

    conv_all<<<(int)((TOTPAIRS + 255) / 256), 256>>>(X, Wq, Wk, Wv, Wo, xh, wh);

    // QKV: 3 z x 11 n-blocks of 192 -> grid (33, 171)
    gemm_fp16<true><<<dim3(3 * NBLK, 171), 256, GEMM_SMEM>>>(xh, wh, bq, bk, bv, qkv,
                                                             WSZ, (long)MTOK * HID);

    attn_fused<<<dim3(2, NT), 256, ATT_SMEM>>>(qkv, ca);

    // O-proj: grid (11, 171)
    gemm_fp16<false><<<dim3(NBLK, 171), 256, GEMM_SMEM>>>(ca, wh + 3 * WSZ, bo, bo, bo, out,
                                                          0, 0);
}

// round 15
// speedup vs baseline: 1.0618x; 1.0426x over previous
#include <cuda_runtime.h>
#include <cuda_fp16.h>
#include <stdint.h>

#define HID  2048
#define B_   4
#define S_   4096
#define P_   256
#define D_   128
#define NT   1024
#define MTOK 16384
#define SCALE 0.08838834764831845f

// ---------------- scratch ----------------------------------------------------
__device__ __half g_xh [(long)MTOK*HID];
__device__ __half g_wh [4][(long)HID*HID];
__device__ __half g_qkv[3][(long)MTOK*HID];
__device__ __half g_ca [(long)MTOK*HID];

__device__ __forceinline__ void cpa16(uint32_t d, const void* g) {
    asm volatile("cp.async.cg.shared.global [%0], [%1], 16;" :: "r"(d), "l"(g));
}
__device__ __forceinline__ uint32_t packh2(float a, float b) {
    __half2 h = __floats2half2_rn(a, b);
    return *(uint32_t*)&h;
}

#define LDSM4(r0,r1,r2,r3, addr) \
    asm volatile("ldmatrix.sync.aligned.m8n8.x4.shared.b16 {%0,%1,%2,%3}, [%4];" \
        : "=r"(r0), "=r"(r1), "=r"(r2), "=r"(r3) : "r"(addr))

#define LDSM4T(r0,r1,r2,r3, addr) \
    asm volatile("ldmatrix.sync.aligned.m8n8.x4.trans.shared.b16 {%0,%1,%2,%3}, [%4];" \
        : "=r"(r0), "=r"(r1), "=r"(r2), "=r"(r3) : "r"(addr))

#define MMA(d, a0,a1,a2,a3, b0,b1) \
    asm volatile("mma.sync.aligned.m16n8k16.row.col.f32.f16.f16.f32 " \
        "{%0,%1,%2,%3}, {%4,%5,%6,%7}, {%8,%9}, {%0,%1,%2,%3};" \
        : "+f"((d)[0]), "+f"((d)[1]), "+f"((d)[2]), "+f"((d)[3]) \
        : "r"(a0), "r"(a1), "r"(a2), "r"(a3), "r"(b0), "r"(b1))

// ---------------- FP16 GEMM: C = A @ W_z^T + bias_z --------------------------
// Block 128x192, 8 warps (2x4) of 64x48 warp tiles, BK=64, 2-stage cp.async,
// 2 CTAs/SM. B/MAC = 0.0729 -> crossbar cap 85.7%.
#define PADH 72
#define ABUF (128 * PADH)           // 9216 halves
#define BBUF (192 * PADH)           // 13824 halves
#define GEMM_SMEM ((2*ABUF + 2*BBUF) * 2)   // 92160 B
#define NBLK 11                     // ceil(2048/192)

template<bool OUT_HALF>
__global__ __launch_bounds__(256, 2)
void gemm_fp16(const __half* __restrict__ A, const __half* __restrict__ Wbase,
               const float* __restrict__ bias0, const float* __restrict__ bias1,
               const float* __restrict__ bias2, void* __restrict__ Cv,
               long sW, long sC)
{
    extern __shared__ __half sgm[];
    __half* As = sgm;              // [2][ABUF]
    __half* Bs = sgm + 2 * ABUF;   // [2][BBUF]

    const int z  = blockIdx.x / NBLK;
    const int n0 = (blockIdx.x % NBLK) * 192;
    const int m0 = blockIdx.y * 128;
    const __half* Bm = Wbase + (long)z * sW;
    const float* bias = (z == 0) ? bias0 : (z == 1) ? bias1 : bias2;

    const int tid  = threadIdx.x;
    const int lane = tid & 31;
    const int wid  = tid >> 5;
    const int wm   = wid >> 2;      // 0..1 -> 64-row slab
    const int wn   = wid & 3;       // 0..3 -> 48-col slab
    const int g    = lane >> 2;
    const int tg   = lane & 3;

    float acc[4][6][4];
#pragma unroll
    for (int i = 0; i < 4; i++)
#pragma unroll
        for (int j = 0; j < 6; j++)
#pragma unroll
            for (int r = 0; r < 4; r++) acc[i][j][r] = 0.f;

    const uint32_t sA0 = (uint32_t)__cvta_generic_to_shared(As);
    const uint32_t sB0 = (uint32_t)__cvta_generic_to_shared(Bs);
    const uint32_t aBase = sA0 + (((wm * 64 + (lane & 15)) * PADH) + (lane >> 4) * 8) * 2;
    const uint32_t bBase = sB0 + (((wn * 48 + (lane & 7) + ((lane >> 4) << 3)) * PADH)
                                  + ((lane >> 3) & 1) * 8) * 2;

    // one BK=64 tile: A 128x64 halves (4 cpa16/thr), B 192x64 halves (6 cpa16/thr)
    auto prefetch = [&](int kt, int buf) {
#pragma unroll
        for (int u = 0; u < 4; u++) {
            int id   = tid + u * 256;        // 0..1023
            int row  = id >> 3;              // 0..127
            int col8 = (id & 7) << 3;
            cpa16((uint32_t)__cvta_generic_to_shared(&As[buf * ABUF + row * PADH + col8]),
                  A + (long)(m0 + row) * HID + kt * 64 + col8);
        }
#pragma unroll
        for (int u = 0; u < 6; u++) {
            int id   = tid + u * 256;        // 0..1535
            int row  = id >> 3;              // 0..191
            int col8 = (id & 7) << 3;
            int rB   = n0 + row; if (rB > HID - 1) rB = HID - 1;   // clamp
            cpa16((uint32_t)__cvta_generic_to_shared(&Bs[buf * BBUF + row * PADH + col8]),
                  Bm + (long)rB * HID + kt * 64 + col8);
        }
        asm volatile("cp.async.commit_group;");
    };

    prefetch(0, 0);

    const int nK = HID >> 6;   // 32 tiles
    for (int t = 0; t < nK; t++) {
        asm volatile("cp.async.wait_group 0;");
        __syncthreads();

        if (t + 1 < nK) prefetch(t + 1, (t + 1) & 1);

        const int buf = t & 1;
        const uint32_t aOff = (uint32_t)(buf * ABUF * 2);
        const uint32_t bOff = (uint32_t)(buf * BBUF * 2);
#pragma unroll
        for (int k0 = 0; k0 < 64; k0 += 16) {
            uint32_t af[4][4], bf[6][2];
            const uint32_t ak = aBase + aOff + k0 * 2;
            const uint32_t bk = bBase + bOff + k0 * 2;
#pragma unroll
            for (int mi = 0; mi < 4; mi++)
                LDSM4(af[mi][0], af[mi][1], af[mi][2], af[mi][3],
                      ak + (uint32_t)(mi * 16 * PADH * 2));
#pragma unroll
            for (int p = 0; p < 3; p++)
                LDSM4(bf[2*p][0], bf[2*p][1], bf[2*p+1][0], bf[2*p+1][1],
                      bk + (uint32_t)(p * 16 * PADH * 2));
#pragma unroll
            for (int mi = 0; mi < 4; mi++)
#pragma unroll
                for (int ni = 0; ni < 6; ni++)
                    MMA(acc[mi][ni], af[mi][0], af[mi][1], af[mi][2], af[mi][3],
                        bf[ni][0], bf[ni][1]);
        }
    }

    const long cOff = (long)z * sC;
#pragma unroll
    for (int mi = 0; mi < 4; mi++) {
#pragma unroll
        for (int ni = 0; ni < 6; ni++) {
            int row = m0 + wm * 64 + mi * 16 + g;
            int col = n0 + wn * 48 + ni * 8 + 2 * tg;
            if (col < HID) {
                float b0 = bias[col], b1 = bias[col + 1];
                float v00 = acc[mi][ni][0] + b0;
                float v01 = acc[mi][ni][1] + b1;
                float v10 = acc[mi][ni][2] + b0;
                float v11 = acc[mi][ni][3] + b1;
                if (OUT_HALF) {
                    __half* C = (__half*)Cv + cOff;
                    *(__half2*)(C + (long)row * HID + col)       = __floats2half2_rn(v00, v01);
                    *(__half2*)(C + (long)(row + 8) * HID + col) = __floats2half2_rn(v10, v11);
                } else {
                    float* C = (float*)Cv + cOff;
                    *(float2*)(C + (long)row * HID + col)       = make_float2(v00, v01);
                    *(float2*)(C + (long)(row + 8) * HID + col) = make_float2(v10, v11);
                }
            }
        }
    }
}

// ---------------- fused attention, direct load from g_qkv --------------------
#define PADQ 72
#define PADK 136
#define PADV 136
#define ATT_SMEM ((256*PADQ + 256*PADK + 256*PADV) * 2)   // 176128

__global__ __launch_bounds__(256, 1)
void attn_fused(const __half* __restrict__ qkv, __half* __restrict__ ca)
{
    extern __shared__ __half smn[];
    const int t = blockIdx.y, mh = blockIdx.x;
    const int b = t >> 8, h = (t >> 4) & 15, n = t & 15;
    const int tid = threadIdx.x, lane = tid & 31, w = tid >> 5;
    const int jq = w >> 2, q = w & 3;

    const long rowbase = (long)(b * S_ + n * 256) * HID;
    const __half* qg = qkv + rowbase + h * 128 + mh * 64;
    const __half* kg = qkv + (long)MTOK * HID + rowbase + h * 128;
    const __half* vg = qkv + 2 * (long)MTOK * HID + rowbase + h * 128;

    const uint32_t qsu = (uint32_t)__cvta_generic_to_shared(smn);
    const uint32_t ksu = qsu + 256 * PADQ * 2;
    const uint32_t vsu = ksu + 256 * PADK * 2;

#pragma unroll
    for (int u = 0; u < 8; u++) {
        int id = tid + u * 256, row = id >> 3, seg = id & 7;
        cpa16(qsu + (row * PADQ + seg * 8) * 2, qg + (long)row * HID + seg * 8);
    }
#pragma unroll
    for (int u = 0; u < 8; u++) {
        int id = tid + u * 256, rr = id >> 4, seg = id & 15;
        int row = (rr & 63) + (rr >> 6) * 128;
        cpa16(ksu + (row * PADK + seg * 8) * 2, kg + (long)row * HID + seg * 8);
    }
    asm volatile("cp.async.commit_group;");
#pragma unroll
    for (int u = 0; u < 8; u++) {
        int id = tid + u * 256, rr = id >> 4, seg = id & 15;
        int row = 64 + (rr & 63) + (rr >> 6) * 128;
        cpa16(ksu + (row * PADK + seg * 8) * 2, kg + (long)row * HID + seg * 8);
    }
    asm volatile("cp.async.commit_group;");
#pragma unroll
    for (int u = 0; u < 16; u++) {
        int id = tid + u * 256, row = id >> 4, seg = id & 15;
        cpa16(vsu + (row * PADV + seg * 8) * 2, vg + (long)row * HID + seg * 8);
    }
    asm volatile("cp.async.commit_group;");

    const uint32_t aB = qsu + (((jq * 128 + (lane & 7) + ((lane >> 4) & 1) * 8) * PADQ)
                               + q * 16 + ((lane >> 3) & 1) * 8) * 2;
    const uint32_t kB = ksu + ((((lane & 7) + ((lane >> 3) & 1) * 8) * PADK)
                               + (lane >> 4) * 8) * 2;
    const uint32_t vB = vsu + ((((lane & 7) + ((lane >> 4) & 1) * 8) * PADV)
                               + ((lane >> 3) & 1) * 8) * 2;

    float acc[32][4];
#pragma unroll
    for (int i = 0; i < 32; i++)
        acc[i][0] = acc[i][1] = acc[i][2] = acc[i][3] = 0.f;

    asm volatile("cp.async.wait_group 2;");
    __syncthreads();

    uint32_t qa[8][4];
#pragma unroll
    for (int kk = 0; kk < 8; kk++)
        LDSM4T(qa[kk][0], qa[kk][1], qa[kk][2], qa[kk][3],
               aB + (uint32_t)(kk * 16 * PADQ * 2));

#pragma unroll
    for (int kk = 0; kk < 8; kk++) {
        if (kk == 4) { asm volatile("cp.async.wait_group 1;"); __syncthreads(); }
#pragma unroll
        for (int jk = 0; jk < 2; jk++) {
#pragma unroll
            for (int p = 0; p < 8; p++) {
                uint32_t b0, b1, b2, b3;
                LDSM4T(b0, b1, b2, b3,
                       kB + (uint32_t)(((jk * 128 + kk * 16) * PADK + p * 16) * 2));
                MMA(acc[jk*16 + 2*p],     qa[kk][0], qa[kk][1], qa[kk][2], qa[kk][3], b0, b1);
                MMA(acc[jk*16 + 2*p + 1], qa[kk][0], qa[kk][1], qa[kk][2], qa[kk][3], b2, b3);
            }
        }
    }

    float mx0 = -1e30f, mx1 = -1e30f;
#pragma unroll
    for (int i = 0; i < 32; i++) {
        mx0 = fmaxf(mx0, fmaxf(acc[i][0], acc[i][1]));
        mx1 = fmaxf(mx1, fmaxf(acc[i][2], acc[i][3]));
    }
    mx0 = fmaxf(mx0, __shfl_xor_sync(~0u, mx0, 1));
    mx0 = fmaxf(mx0, __shfl_xor_sync(~0u, mx0, 2));
    mx1 = fmaxf(mx1, __shfl_xor_sync(~0u, mx1, 1));
    mx1 = fmaxf(mx1, __shfl_xor_sync(~0u, mx1, 2));
    float s0 = 0.f, s1 = 0.f;
#pragma unroll
    for (int i = 0; i < 32; i++) {
        acc[i][0] = __expf((acc[i][0] - mx0) * SCALE);
        acc[i][1] = __expf((acc[i][1] - mx0) * SCALE);
        acc[i][2] = __expf((acc[i][2] - mx1) * SCALE);
        acc[i][3] = __expf((acc[i][3] - mx1) * SCALE);
        s0 += acc[i][0] + acc[i][1];
        s1 += acc[i][2] + acc[i][3];
    }
    s0 += __shfl_xor_sync(~0u, s0, 1); s0 += __shfl_xor_sync(~0u, s0, 2);
    s1 += __shfl_xor_sync(~0u, s1, 1); s1 += __shfl_xor_sync(~0u, s1, 2);
    const float inv0 = 1.f / s0, inv1 = 1.f / s1;

    asm volatile("cp.async.wait_group 0;");
    __syncthreads();

    float o[16][4];
#pragma unroll
    for (int i = 0; i < 16; i++)
        o[i][0] = o[i][1] = o[i][2] = o[i][3] = 0.f;

#pragma unroll
    for (int jk = 0; jk < 2; jk++) {
#pragma unroll
        for (int kk2 = 0; kk2 < 8; kk2++) {
            const int t0 = jk * 16 + 2 * kk2, t1 = t0 + 1;
            uint32_t a0 = packh2(acc[t0][0] * inv0, acc[t0][1] * inv0);
            uint32_t a1 = packh2(acc[t0][2] * inv1, acc[t0][3] * inv1);
            uint32_t a2 = packh2(acc[t1][0] * inv0, acc[t1][1] * inv0);
            uint32_t a3 = packh2(acc[t1][2] * inv1, acc[t1][3] * inv1);
#pragma unroll
            for (int p2 = 0; p2 < 8; p2++) {
                uint32_t b0, b1, b2, b3;
                LDSM4(b0, b1, b2, b3,
                      vB + (uint32_t)((((jk * 128 + p2 * 16) * PADV) + kk2 * 16) * 2));
                MMA(o[2*p2],     a0, a1, a2, a3, b0, b1);
                MMA(o[2*p2 + 1], a0, a1, a2, a3, b2, b3);
            }
        }
    }

    const int g = lane >> 2, tg = lane & 3;
    const int p2row = 2 * (mh * 64 + q * 16 + g) + jq;
    __half* cbase = ca + ((long)(b * 4096 + h * 256)) * HID + n * 128;
#pragma unroll
    for (int ni = 0; ni < 16; ni++) {
        int d2 = ni * 8 + 2 * tg;
        *(__half2*)(cbase + (long)p2row * HID + d2)        = __floats2half2_rn(o[ni][0], o[ni][1]);
        *(__half2*)(cbase + (long)(p2row + 16) * HID + d2) = __floats2half2_rn(o[ni][2], o[ni][3]);
    }
}

// ---------------- fused f32->f16 conversion, 2 float4 per thread -------------
#define XN4 ((long)MTOK * HID / 4)
#define WN4 ((long)HID * HID / 4)
#define TOTPAIRS ((XN4 + 4 * WN4) / 2)
__global__ void conv_all(const float* __restrict__ X,
                         const float* __restrict__ W0, const float* __restrict__ W1,
                         const float* __restrict__ W2, const float* __restrict__ W3,
                         __half* __restrict__ xh, __half* __restrict__ wh)
{
    long p = (long)blockIdx.x * 256 + threadIdx.x;
    if (p >= TOTPAIRS) return;
    long i = p * 2;
    const float* src;
    __half* dst;
    long idx;
    if (i < XN4) {
        src = X; dst = xh; idx = i;
    } else {
        long j = i - XN4;
        int wsel = (int)(j / WN4);
        src = (wsel == 0) ? W0 : (wsel == 1) ? W1 : (wsel == 2) ? W2 : W3;
        dst = wh + (long)wsel * (WN4 * 4);
        idx = j - (long)wsel * WN4;
    }
    float4 v0 = ((const float4*)src)[idx];
    float4 v1 = ((const float4*)src)[idx + 1];
    uint4 o;
    o.x = packh2(v0.x, v0.y);
    o.y = packh2(v0.z, v0.w);
    o.z = packh2(v1.x, v1.y);
    o.w = packh2(v1.z, v1.w);
    *(uint4*)(dst + idx * 4) = o;
}

// ---------------- launch -------------------------------------------------------
extern "C" void kernel_launch(void* const* d_in, const int* in_sizes, int n_in,
                              void* d_out, int out_size)
{
    const float* X  = (const float*)d_in[0];
    const float* Wq = (const float*)d_in[1];
    const float* bq = (const float*)d_in[2];
    const float* Wk = (const float*)d_in[3];
    const float* bk = (const float*)d_in[4];
    const float* Wv = (const float*)d_in[5];
    const float* bv = (const float*)d_in[6];
    const float* Wo = (const float*)d_in[7];
    const float* bo = (const float*)d_in[8];
    float* out = (float*)d_out;

    __half *xh, *wh, *qkv, *ca;
    cudaGetSymbolAddress((void**)&xh,  g_xh);
    cudaGetSymbolAddress((void**)&wh,  g_wh);
    cudaGetSymbolAddress((void**)&qkv, g_qkv);
    cudaGetSymbolAddress((void**)&ca,  g_ca);

    cudaFuncSetAttribute(attn_fused, cudaFuncAttributeMaxDynamicSharedMemorySize, ATT_SMEM);
    cudaFuncSetAttribute(gemm_fp16<true>,  cudaFuncAttributeMaxDynamicSharedMemorySize, GEMM_SMEM);
    cudaFuncSetAttribute(gemm_fp16<false>, cudaFuncAttributeMaxDynamicSharedMemorySize, GEMM_SMEM);

    const long WSZ = (long)HID * HID;

    conv_all<<<(int)((TOTPAIRS + 255) / 256), 256>>>(X, Wq, Wk, Wv, Wo, xh, wh);

    // QKV: 3 z x 11 n-blocks of 192 -> grid (33, 128)
    gemm_fp16<true><<<dim3(3 * NBLK, 128), 256, GEMM_SMEM>>>(xh, wh, bq, bk, bv, qkv,
                                                             WSZ, (long)MTOK * HID);

    attn_fused<<<dim3(2, NT), 256, ATT_SMEM>>>(qkv, ca);

    // O-proj: grid (11, 128)
    gemm_fp16<false><<<dim3(NBLK, 128), 256, GEMM_SMEM>>>(ca, wh + 3 * WSZ, bo, bo, bo, out,
                                                          0, 0);
}